// round 1
// baseline (speedup 1.0000x reference)
#include <cuda_runtime.h>

#define EMB_DIM 128
#define NB_WORDS 100000

// out[b][e] = W[e * NB_WORDS + elt[b]] + bias[e]
// Grid: one block per 4 batch rows, 512 threads (4 x 128).
__global__ void time_embedding_kernel(const int* __restrict__ elt,
                                      const float* __restrict__ W,
                                      const float* __restrict__ bias,
                                      float* __restrict__ out,
                                      int batch) {
    const int e = threadIdx.x & (EMB_DIM - 1);       // 0..127
    const int sub = threadIdx.x >> 7;                 // 0..3 (row within block)
    const int b = blockIdx.x * 4 + sub;
    if (b >= batch) return;

    const int idx = __ldg(&elt[b]);                   // uniform within 128-thread group
    const float w = __ldg(&W[(size_t)e * NB_WORDS + idx]);
    const float bv = __ldg(&bias[e]);
    out[(size_t)b * EMB_DIM + e] = w + bv;
}

extern "C" void kernel_launch(void* const* d_in, const int* in_sizes, int n_in,
                              void* d_out, int out_size) {
    const int* elt  = (const int*)d_in[0];
    const float* W  = (const float*)d_in[1];
    const float* bv = (const float*)d_in[2];
    float* out      = (float*)d_out;

    const int batch = in_sizes[0];                    // 4096
    const int blocks = (batch + 3) / 4;
    time_embedding_kernel<<<blocks, 512>>>(elt, W, bv, out, batch);
}